// round 8
// baseline (speedup 1.0000x reference)
#include <cuda_runtime.h>
#include <math.h>

#define NN 8192
#define TPB 256
#define JCH 64                  // j chunks for the pair kernel
#define JTILE (NN / JCH)        // 128 j per tile
#define JT2 (JTILE / 2)         // 64 packed j-pairs per tile
#define IBLK2 (NN / (2 * TPB))  // 16 i-blocks (each thread owns 2 i's)
#define IBLK (NN / TPB)         // 32 blocks for k_prep
#define NPB (IBLK2 * JCH)       // 1024 pair blocks

// ---------------- device scratch (no allocations allowed) ----------------
__device__ float  g_wm[NN];              // weights * (label==0)
__device__ float  g_Ra[NN];              // row sums: sum_j wm_j |x_i - x_j|
__device__ float  g_Rb[NN];              // row sums: sum_j wm_j |y_i - y_j|
__device__ double g_prep_part[IBLK][8];  // per-block: bce,nf,sw,swx,swx2,swy,swy2
__device__ double g_tab_part[NPB];       // per-block T_ab partials
__device__ int    g_count = 0;           // completion counter for last-block epilogue

// ---------------- packed f32x2 helpers (sm_103a FFMA2 path) ----------------
typedef unsigned long long u64;
#define ABS2 0x7FFFFFFF7FFFFFFFULL

__device__ __forceinline__ u64 f2pack(float a, float b) {
    u64 r; asm("mov.b64 %0, {%1, %2};" : "=l"(r) : "f"(a), "f"(b)); return r;
}
__device__ __forceinline__ void f2unpack(u64 v, float& a, float& b) {
    asm("mov.b64 {%0, %1}, %2;" : "=f"(a), "=f"(b) : "l"(v));
}
__device__ __forceinline__ u64 addx2(u64 a, u64 b) {
    u64 r; asm("add.rn.f32x2 %0, %1, %2;" : "=l"(r) : "l"(a), "l"(b)); return r;
}
__device__ __forceinline__ u64 mulx2(u64 a, u64 b) {
    u64 r; asm("mul.rn.f32x2 %0, %1, %2;" : "=l"(r) : "l"(a), "l"(b)); return r;
}
__device__ __forceinline__ u64 fmax2(u64 a, u64 b, u64 c) {
    u64 r; asm("fma.rn.f32x2 %0, %1, %2, %3;" : "=l"(r) : "l"(a), "l"(b), "l"(c)); return r;
}

__device__ __forceinline__ double warp_red_d(double v) {
    #pragma unroll
    for (int s = 16; s > 0; s >>= 1)
        v += __shfl_down_sync(0xFFFFFFFFu, v, s);
    return v;
}

// ---------------- kernel 1: wm, zero row sums, O(N) reductions ----------------
// Writes per-block partials (no atomics -> nothing needs pre-zeroing).
__global__ void k_prep(const float* __restrict__ x, const int* __restrict__ lbl,
                       const float* __restrict__ y, const float* __restrict__ w) {
    __shared__ double sred[8][7];
    int tid = threadIdx.x;
    int i = blockIdx.x * TPB + tid;
    int lane = tid & 31, wid = tid >> 5;

    float xi = x[i];
    float yi = y[i];
    float wi = w[i];
    int   li = lbl[i];

    float m  = (li == 0) ? 1.0f : 0.0f;
    float wm = wi * m;
    g_wm[i] = wm;
    g_Ra[i] = 0.0f;
    g_Rb[i] = 0.0f;

    // BCE term (torch F.binary_cross_entropy with clamp at -100, weighted)
    float yf     = (float)li;
    float logp   = fmaxf(logf(xi), -100.0f);
    float log1mp = fmaxf(log1pf(-xi), -100.0f);
    float bce    = wi * (-(yf * logp + (1.0f - yf) * log1mp));

    double vals[7];
    vals[0] = (double)bce;
    vals[1] = (double)m;                       // nf
    vals[2] = (double)wm;                      // sw
    vals[3] = (double)wm * xi;                 // swx
    vals[4] = (double)wm * xi * xi;            // swx2
    vals[5] = (double)wm * yi;                 // swy
    vals[6] = (double)wm * yi * yi;            // swy2

    #pragma unroll
    for (int k = 0; k < 7; k++) {
        double v = warp_red_d(vals[k]);
        if (lane == 0) sred[wid][k] = v;
    }
    __syncthreads();
    if (wid == 0 && lane < 7) {
        double s = 0.0;
        #pragma unroll
        for (int ww = 0; ww < 8; ww++) s += sred[ww][lane];
        g_prep_part[blockIdx.x][lane] = s;
    }
}

// ---------------- kernel 2: O(N^2) fused pass + last-block epilogue ----------------
__global__ void __launch_bounds__(TPB) k_pairs(const float* __restrict__ x,
                                               const float* __restrict__ y,
                                               float* __restrict__ out) {
    __shared__ ulonglong2 sxy[JT2];   // {(-x_{2k},-x_{2k+1}), (-y_{2k},-y_{2k+1})}
    __shared__ u64 sw2[JT2];          // (wm_{2k}, wm_{2k+1})
    __shared__ double sred[8][5];
    __shared__ bool isLast;

    int tid = threadIdx.x;
    int i0  = blockIdx.x * TPB + tid;
    int i1  = i0 + NN / 2;
    int j0  = blockIdx.y * JTILE;
    int lane = tid & 31, wid = tid >> 5;

    if (tid < JT2) {
        int j = j0 + 2 * tid;
        ulonglong2 v;
        v.x = f2pack(-x[j], -x[j + 1]);
        v.y = f2pack(-y[j], -y[j + 1]);
        sxy[tid] = v;
        sw2[tid] = f2pack(g_wm[j], g_wm[j + 1]);
    }
    __syncthreads();

    float xi0f = x[i0], xi1f = x[i1];
    float yi0f = y[i0], yi1f = y[i1];
    u64 xi0 = f2pack(xi0f, xi0f);
    u64 xi1 = f2pack(xi1f, xi1f);
    u64 yi0 = f2pack(yi0f, yi0f);
    u64 yi1 = f2pack(yi1f, yi1f);

    u64 ra0 = 0ull, rb0 = 0ull, t0 = 0ull;
    u64 ra1 = 0ull, rb1 = 0ull, t1 = 0ull;

    #pragma unroll 4
    for (int k = 0; k < JT2; k++) {
        ulonglong2 v = sxy[k];
        u64 w2 = sw2[k];

        u64 aa0 = addx2(xi0, v.x) & ABS2;   // |x_i0 - x_j| x2
        u64 ab0 = addx2(yi0, v.y) & ABS2;
        u64 u0  = mulx2(w2, aa0);
        ra0 = addx2(ra0, u0);
        rb0 = fmax2(w2, ab0, rb0);
        t0  = fmax2(u0, ab0, t0);

        u64 aa1 = addx2(xi1, v.x) & ABS2;
        u64 ab1 = addx2(yi1, v.y) & ABS2;
        u64 u1  = mulx2(w2, aa1);
        ra1 = addx2(ra1, u1);
        rb1 = fmax2(w2, ab1, rb1);
        t1  = fmax2(u1, ab1, t1);
    }

    float lo, hi;
    f2unpack(ra0, lo, hi); float raf0 = lo + hi;
    f2unpack(rb0, lo, hi); float rbf0 = lo + hi;
    f2unpack(t0,  lo, hi); float tf0  = lo + hi;
    f2unpack(ra1, lo, hi); float raf1 = lo + hi;
    f2unpack(rb1, lo, hi); float rbf1 = lo + hi;
    f2unpack(t1,  lo, hi); float tf1  = lo + hi;

    atomicAdd(&g_Ra[i0], raf0);
    atomicAdd(&g_Rb[i0], rbf0);
    atomicAdd(&g_Ra[i1], raf1);
    atomicAdd(&g_Rb[i1], rbf1);

    // T_ab partial, weighted by wm_i -> per-block slot (no atomic)
    double tp = (double)(g_wm[i0] * tf0) + (double)(g_wm[i1] * tf1);
    tp = warp_red_d(tp);
    if (lane == 0) sred[wid][0] = tp;
    __syncthreads();
    if (tid == 0) {
        double s = 0.0;
        #pragma unroll
        for (int ww = 0; ww < TPB / 32; ww++) s += sred[ww][0];
        g_tab_part[blockIdx.y * IBLK2 + blockIdx.x] = s;
        // make this block's global writes visible, then count completion
        __threadfence();
        int c = atomicAdd(&g_count, 1);
        isLast = (c == NPB - 1);
    }
    __syncthreads();

    if (!isLast) return;

    // =========== last-block epilogue: all O(N) reductions + combine ===========
    __threadfence();   // pair with writers' fences (acquire side)

    // 1) per-i DP reductions over Ra/Rb
    double va = 0.0, vb = 0.0, uab = 0.0, uaa = 0.0, ubb = 0.0, tab = 0.0;
    for (int i = tid; i < NN; i += TPB) {
        double wm = (double)g_wm[i];
        double Ra = (double)g_Ra[i];
        double Rb = (double)g_Rb[i];
        va  += wm * Ra;
        vb  += wm * Rb;
        uab += wm * Ra * Rb;
        uaa += wm * Ra * Ra;
        ubb += wm * Rb * Rb;
    }
    // fold T_ab partial sum into same reduction round
    for (int k = tid; k < NPB; k += TPB) tab += g_tab_part[k];

    va  = warp_red_d(va);
    vb  = warp_red_d(vb);
    uab = warp_red_d(uab);
    uaa = warp_red_d(uaa);
    ubb = warp_red_d(ubb);
    tab = warp_red_d(tab);
    if (lane == 0) {
        sred[wid][0] = va;  sred[wid][1] = vb;  sred[wid][2] = uab;
        sred[wid][3] = uaa; sred[wid][4] = ubb;
    }
    __shared__ double stab[8];
    if (lane == 0) stab[wid] = tab;
    __syncthreads();

    if (tid == 0) {
        double VA = 0, VB = 0, UAB = 0, UAA = 0, UBB = 0, TAB = 0;
        #pragma unroll
        for (int ww = 0; ww < 8; ww++) {
            VA  += sred[ww][0]; VB  += sred[ww][1]; UAB += sred[ww][2];
            UAA += sred[ww][3]; UBB += sred[ww][4]; TAB += stab[ww];
        }
        // 2) prep partials
        double bce_sum = 0, nf = 0, sw = 0, swx = 0, swx2 = 0, swy = 0, swy2 = 0;
        for (int b = 0; b < IBLK; b++) {
            bce_sum += g_prep_part[b][0];
            nf      += g_prep_part[b][1];
            sw      += g_prep_part[b][2];
            swx     += g_prep_part[b][3];
            swx2    += g_prep_part[b][4];
            swy     += g_prep_part[b][5];
            swy2    += g_prep_part[b][6];
        }

        // closed forms for sum_ij wm_i wm_j (dx)^2 and (dy)^2
        double Taa = 2.0 * (sw * swx2 - swx * swx);
        double Tbb = 2.0 * (sw * swy2 - swy * swy);

        // Full weighted double-centering expansion (sw != nf!):
        //   <A.B> = Tab - (4/nf - 2*sw/nf^2) * uab + c * va*vb
        //   c     = (4 - 4*sw/nf + (sw/nf)^2) / nf^2
        double inv_nf = 1.0 / nf;
        double r      = sw * inv_nf;
        double coef_u = (4.0 - 2.0 * r) * inv_nf;
        double c      = (4.0 - 4.0 * r + r * r) * inv_nf * inv_nf;

        double Eab = TAB - coef_u * UAB + c * VA * VB;
        double Eaa = Taa - coef_u * UAA + c * VA * VA;
        double Ebb = Tbb - coef_u * UBB + c * VB * VB;

        // the /nf^2 normalizations cancel in the ratio
        double dcorr = (Eab * Eab) / (Eaa * Ebb);   // DCORR_POWER == 2
        double bce   = bce_sum / (double)NN;
        double disco = 0.1 * dcorr;                 // DISCO_LAMBDA

        out[0] = (float)(bce + disco);
        out[1] = (float)bce;
        out[2] = (float)disco;

        g_count = 0;   // reset for next graph replay
    }
}

// ---------------- launch ----------------
extern "C" void kernel_launch(void* const* d_in, const int* in_sizes, int n_in,
                              void* d_out, int out_size) {
    const float* inferences   = (const float*)d_in[0];
    const int*   labels       = (const int*)d_in[1];
    const float* disco_target = (const float*)d_in[2];
    const float* weights      = (const float*)d_in[3];
    float* out = (float*)d_out;

    k_prep<<<IBLK, TPB>>>(inferences, labels, disco_target, weights);
    k_pairs<<<dim3(IBLK2, JCH), TPB>>>(inferences, disco_target, out);
}

// round 9
// speedup vs baseline: 1.3684x; 1.3684x over previous
#include <cuda_runtime.h>
#include <math.h>

#define NN 8192
#define TPB 256
#define JCH 64                  // j chunks for the pair kernel
#define JTILE (NN / JCH)        // 128 j per tile
#define JT2 (JTILE / 2)         // 64 packed j-pairs per tile
#define IBLK2 (NN / (2 * TPB))  // 16 i-blocks (each thread owns 2 i's)
#define IBLK (NN / TPB)         // 32 blocks for O(N) kernels
#define NPB (IBLK2 * JCH)       // 1024 pair blocks

// ---------------- device scratch (no allocations allowed) ----------------
__device__ float  g_wm[NN];              // weights * (label==0)
__device__ float  g_Ra[NN];              // row sums: sum_j wm_j |x_i - x_j|
__device__ float  g_Rb[NN];              // row sums: sum_j wm_j |y_i - y_j|
__device__ double g_prep_part[IBLK][8];  // per-block: bce,nf,sw,swx,swx2,swy,swy2
__device__ double g_tab_part[NPB];       // per-block T_ab partials
__device__ double g_epi_part[IBLK][5];   // per-block: va,vb,uab,uaa,ubb
__device__ int    g_count = 0;           // completion counter (k_epi last block)

// ---------------- packed f32x2 helpers (sm_103a FFMA2 path) ----------------
typedef unsigned long long u64;
#define ABS2 0x7FFFFFFF7FFFFFFFULL

__device__ __forceinline__ u64 f2pack(float a, float b) {
    u64 r; asm("mov.b64 %0, {%1, %2};" : "=l"(r) : "f"(a), "f"(b)); return r;
}
__device__ __forceinline__ void f2unpack(u64 v, float& a, float& b) {
    asm("mov.b64 {%0, %1}, %2;" : "=f"(a), "=f"(b) : "l"(v));
}
__device__ __forceinline__ u64 addx2(u64 a, u64 b) {
    u64 r; asm("add.rn.f32x2 %0, %1, %2;" : "=l"(r) : "l"(a), "l"(b)); return r;
}
__device__ __forceinline__ u64 mulx2(u64 a, u64 b) {
    u64 r; asm("mul.rn.f32x2 %0, %1, %2;" : "=l"(r) : "l"(a), "l"(b)); return r;
}
__device__ __forceinline__ u64 fmax2(u64 a, u64 b, u64 c) {
    u64 r; asm("fma.rn.f32x2 %0, %1, %2, %3;" : "=l"(r) : "l"(a), "l"(b), "l"(c)); return r;
}

__device__ __forceinline__ double warp_red_d(double v) {
    #pragma unroll
    for (int s = 16; s > 0; s >>= 1)
        v += __shfl_down_sync(0xFFFFFFFFu, v, s);
    return v;
}

// ---------------- kernel 1: wm, zero row sums, O(N) reductions ----------------
// Writes per-block partials (no atomics -> nothing needs pre-zeroing).
__global__ void k_prep(const float* __restrict__ x, const int* __restrict__ lbl,
                       const float* __restrict__ y, const float* __restrict__ w) {
    __shared__ double sred[8][7];
    int tid = threadIdx.x;
    int i = blockIdx.x * TPB + tid;
    int lane = tid & 31, wid = tid >> 5;

    float xi = x[i];
    float yi = y[i];
    float wi = w[i];
    int   li = lbl[i];

    float m  = (li == 0) ? 1.0f : 0.0f;
    float wm = wi * m;
    g_wm[i] = wm;
    g_Ra[i] = 0.0f;
    g_Rb[i] = 0.0f;

    // BCE term (torch F.binary_cross_entropy with clamp at -100, weighted)
    float yf     = (float)li;
    float logp   = fmaxf(logf(xi), -100.0f);
    float log1mp = fmaxf(log1pf(-xi), -100.0f);
    float bce    = wi * (-(yf * logp + (1.0f - yf) * log1mp));

    double vals[7];
    vals[0] = (double)bce;
    vals[1] = (double)m;                       // nf
    vals[2] = (double)wm;                      // sw
    vals[3] = (double)wm * xi;                 // swx
    vals[4] = (double)wm * xi * xi;            // swx2
    vals[5] = (double)wm * yi;                 // swy
    vals[6] = (double)wm * yi * yi;            // swy2

    #pragma unroll
    for (int k = 0; k < 7; k++) {
        double v = warp_red_d(vals[k]);
        if (lane == 0) sred[wid][k] = v;
    }
    __syncthreads();
    if (wid == 0 && lane < 7) {
        double s = 0.0;
        #pragma unroll
        for (int ww = 0; ww < 8; ww++) s += sred[ww][lane];
        g_prep_part[blockIdx.x][lane] = s;
    }
}

// ---------------- kernel 2: the O(N^2) fused pass (packed f32x2) ----------------
// EXACT R5 shape (codegen-sensitive!) — only delta: per-block tab store, no atomic.
__global__ void __launch_bounds__(TPB) k_pairs(const float* __restrict__ x,
                                               const float* __restrict__ y) {
    __shared__ ulonglong2 sxy[JT2];   // {(-x_{2k},-x_{2k+1}), (-y_{2k},-y_{2k+1})}
    __shared__ u64 sw2[JT2];          // (wm_{2k}, wm_{2k+1})
    __shared__ double sred[TPB / 32];

    int tid = threadIdx.x;
    int i0  = blockIdx.x * TPB + tid;
    int i1  = i0 + NN / 2;
    int j0  = blockIdx.y * JTILE;
    int lane = tid & 31, wid = tid >> 5;

    if (tid < JT2) {
        int j = j0 + 2 * tid;
        ulonglong2 v;
        v.x = f2pack(-x[j], -x[j + 1]);
        v.y = f2pack(-y[j], -y[j + 1]);
        sxy[tid] = v;
        sw2[tid] = f2pack(g_wm[j], g_wm[j + 1]);
    }
    __syncthreads();

    float xi0f = x[i0], xi1f = x[i1];
    float yi0f = y[i0], yi1f = y[i1];
    u64 xi0 = f2pack(xi0f, xi0f);
    u64 xi1 = f2pack(xi1f, xi1f);
    u64 yi0 = f2pack(yi0f, yi0f);
    u64 yi1 = f2pack(yi1f, yi1f);

    u64 ra0 = 0ull, rb0 = 0ull, t0 = 0ull;
    u64 ra1 = 0ull, rb1 = 0ull, t1 = 0ull;

    #pragma unroll 4
    for (int k = 0; k < JT2; k++) {
        ulonglong2 v = sxy[k];
        u64 w2 = sw2[k];

        u64 aa0 = addx2(xi0, v.x) & ABS2;   // |x_i0 - x_j| x2
        u64 ab0 = addx2(yi0, v.y) & ABS2;
        u64 u0  = mulx2(w2, aa0);
        ra0 = addx2(ra0, u0);
        rb0 = fmax2(w2, ab0, rb0);
        t0  = fmax2(u0, ab0, t0);

        u64 aa1 = addx2(xi1, v.x) & ABS2;
        u64 ab1 = addx2(yi1, v.y) & ABS2;
        u64 u1  = mulx2(w2, aa1);
        ra1 = addx2(ra1, u1);
        rb1 = fmax2(w2, ab1, rb1);
        t1  = fmax2(u1, ab1, t1);
    }

    float lo, hi;
    f2unpack(ra0, lo, hi); float raf0 = lo + hi;
    f2unpack(rb0, lo, hi); float rbf0 = lo + hi;
    f2unpack(t0,  lo, hi); float tf0  = lo + hi;
    f2unpack(ra1, lo, hi); float raf1 = lo + hi;
    f2unpack(rb1, lo, hi); float rbf1 = lo + hi;
    f2unpack(t1,  lo, hi); float tf1  = lo + hi;

    atomicAdd(&g_Ra[i0], raf0);
    atomicAdd(&g_Rb[i0], rbf0);
    atomicAdd(&g_Ra[i1], raf1);
    atomicAdd(&g_Rb[i1], rbf1);

    // T_ab partial, weighted by wm_i, block-reduced in double -> per-block slot
    double tp = (double)(g_wm[i0] * tf0) + (double)(g_wm[i1] * tf1);
    tp = warp_red_d(tp);
    if (lane == 0) sred[wid] = tp;
    __syncthreads();
    if (tid == 0) {
        double s = 0.0;
        #pragma unroll
        for (int ww = 0; ww < TPB / 32; ww++) s += sred[ww];
        g_tab_part[blockIdx.y * IBLK2 + blockIdx.x] = s;
    }
}

// ---------------- kernel 3: O(N) epilogue + last-block combine ----------------
__global__ void k_epi(float* __restrict__ out) {
    __shared__ double sred[8][5];
    __shared__ bool isLast;
    int tid = threadIdx.x;
    int i = blockIdx.x * TPB + tid;
    int lane = tid & 31, wid = tid >> 5;

    double wm = (double)g_wm[i];
    double Ra = (double)g_Ra[i];
    double Rb = (double)g_Rb[i];

    double vals[5];
    vals[0] = wm * Ra;            // va
    vals[1] = wm * Rb;            // vb
    vals[2] = wm * Ra * Rb;       // uab
    vals[3] = wm * Ra * Ra;       // uaa
    vals[4] = wm * Rb * Rb;       // ubb

    #pragma unroll
    for (int k = 0; k < 5; k++) {
        double v = warp_red_d(vals[k]);
        if (lane == 0) sred[wid][k] = v;
    }
    __syncthreads();
    if (wid == 0 && lane < 5) {
        double s = 0.0;
        #pragma unroll
        for (int ww = 0; ww < 8; ww++) s += sred[ww][lane];
        g_epi_part[blockIdx.x][lane] = s;
    }
    if (tid == 0) {
        __threadfence();
        int c = atomicAdd(&g_count, 1);
        isLast = (c == IBLK - 1);
    }
    __syncthreads();
    if (!isLast) return;

    // ---- last block: gather all partials and combine ----
    __threadfence();

    // sum the 1024 T_ab partials in parallel
    double tab = 0.0;
    for (int k = tid; k < NPB; k += TPB) tab += g_tab_part[k];
    tab = warp_red_d(tab);
    __shared__ double stab[8];
    if (lane == 0) stab[wid] = tab;
    __syncthreads();

    if (tid == 0) {
        double TAB = 0;
        #pragma unroll
        for (int ww = 0; ww < 8; ww++) TAB += stab[ww];

        double VA = 0, VB = 0, UAB = 0, UAA = 0, UBB = 0;
        for (int b = 0; b < IBLK; b++) {
            VA  += g_epi_part[b][0];
            VB  += g_epi_part[b][1];
            UAB += g_epi_part[b][2];
            UAA += g_epi_part[b][3];
            UBB += g_epi_part[b][4];
        }
        double bce_sum = 0, nf = 0, sw = 0, swx = 0, swx2 = 0, swy = 0, swy2 = 0;
        for (int b = 0; b < IBLK; b++) {
            bce_sum += g_prep_part[b][0];
            nf      += g_prep_part[b][1];
            sw      += g_prep_part[b][2];
            swx     += g_prep_part[b][3];
            swx2    += g_prep_part[b][4];
            swy     += g_prep_part[b][5];
            swy2    += g_prep_part[b][6];
        }

        // closed forms for sum_ij wm_i wm_j (dx)^2 and (dy)^2
        double Taa = 2.0 * (sw * swx2 - swx * swx);
        double Tbb = 2.0 * (sw * swy2 - swy * swy);

        // Full weighted double-centering expansion (sw != nf!):
        //   <A.B> = Tab - (4/nf - 2*sw/nf^2) * uab + c * va*vb
        //   c     = (4 - 4*sw/nf + (sw/nf)^2) / nf^2
        double inv_nf = 1.0 / nf;
        double r      = sw * inv_nf;
        double coef_u = (4.0 - 2.0 * r) * inv_nf;
        double c      = (4.0 - 4.0 * r + r * r) * inv_nf * inv_nf;

        double Eab = TAB - coef_u * UAB + c * VA * VB;
        double Eaa = Taa - coef_u * UAA + c * VA * VA;
        double Ebb = Tbb - coef_u * UBB + c * VB * VB;

        // the /nf^2 normalizations cancel in the ratio
        double dcorr = (Eab * Eab) / (Eaa * Ebb);   // DCORR_POWER == 2
        double bce   = bce_sum / (double)NN;
        double disco = 0.1 * dcorr;                 // DISCO_LAMBDA

        out[0] = (float)(bce + disco);
        out[1] = (float)bce;
        out[2] = (float)disco;

        g_count = 0;   // reset for next graph replay
    }
}

// ---------------- launch ----------------
extern "C" void kernel_launch(void* const* d_in, const int* in_sizes, int n_in,
                              void* d_out, int out_size) {
    const float* inferences   = (const float*)d_in[0];
    const int*   labels       = (const int*)d_in[1];
    const float* disco_target = (const float*)d_in[2];
    const float* weights      = (const float*)d_in[3];
    float* out = (float*)d_out;

    k_prep<<<IBLK, TPB>>>(inferences, labels, disco_target, weights);
    k_pairs<<<dim3(IBLK2, JCH), TPB>>>(inferences, disco_target);
    k_epi<<<IBLK, TPB>>>(out);
}

// round 11
// speedup vs baseline: 1.7837x; 1.3035x over previous
#include <cuda_runtime.h>
#include <math.h>

#define NN 8192
#define TPB 256
#define JCH 64                  // j chunks for the pair kernel
#define JTILE (NN / JCH)        // 128 j per tile
#define JT2 (JTILE / 2)         // 64 packed j-pairs per tile
#define IBLK2 (NN / (2 * TPB))  // 16 i-blocks (each thread owns 2 i's)
#define IBLK 32                 // blocks for the epilogue kernel
#define NPB (IBLK2 * JCH)       // 1024 pair blocks
#define NQ 12                   // reduced quantities in k_epi

// ---------------- device scratch (no allocations allowed) ----------------
// Per-jchunk row-sum partial planes: slot [k][i] written exactly once by the
// block owning (i-range, jchunk k) -> no zeroing, no atomics needed.
__device__ float  g_RaP[JCH][NN];
__device__ float  g_RbP[JCH][NN];
__device__ double g_tab_part[NPB];       // per-pair-block T_ab partials
__device__ double g_epi_part[IBLK][NQ];  // per-epi-block partials
__device__ int    g_count = 0;           // completion counter (k_epi last block)

// ---------------- packed f32x2 helpers (sm_103a FFMA2 path) ----------------
typedef unsigned long long u64;
#define ABS2 0x7FFFFFFF7FFFFFFFULL

__device__ __forceinline__ u64 f2pack(float a, float b) {
    u64 r; asm("mov.b64 %0, {%1, %2};" : "=l"(r) : "f"(a), "f"(b)); return r;
}
__device__ __forceinline__ void f2unpack(u64 v, float& a, float& b) {
    asm("mov.b64 {%0, %1}, %2;" : "=f"(a), "=f"(b) : "l"(v));
}
__device__ __forceinline__ u64 addx2(u64 a, u64 b) {
    u64 r; asm("add.rn.f32x2 %0, %1, %2;" : "=l"(r) : "l"(a), "l"(b)); return r;
}
__device__ __forceinline__ u64 mulx2(u64 a, u64 b) {
    u64 r; asm("mul.rn.f32x2 %0, %1, %2;" : "=l"(r) : "l"(a), "l"(b)); return r;
}
__device__ __forceinline__ u64 fmax2(u64 a, u64 b, u64 c) {
    u64 r; asm("fma.rn.f32x2 %0, %1, %2, %3;" : "=l"(r) : "l"(a), "l"(b), "l"(c)); return r;
}

__device__ __forceinline__ double warp_red_d(double v) {
    #pragma unroll
    for (int s = 16; s > 0; s >>= 1)
        v += __shfl_down_sync(0xFFFFFFFFu, v, s);
    return v;
}

// ---------------- kernel 1: the O(N^2) fused pass (packed f32x2) ----------------
// NO dependencies: wm recomputed inline; row sums -> private partial planes.
// Inner loop identical to R5.
__global__ void __launch_bounds__(TPB) k_pairs(const float* __restrict__ x,
                                               const int*   __restrict__ lbl,
                                               const float* __restrict__ y,
                                               const float* __restrict__ w) {
    __shared__ ulonglong2 sxy[JT2];   // {(-x_{2k},-x_{2k+1}), (-y_{2k},-y_{2k+1})}
    __shared__ u64 sw2[JT2];          // (wm_{2k}, wm_{2k+1})
    __shared__ double sred[TPB / 32];

    int tid = threadIdx.x;
    int i0  = blockIdx.x * TPB + tid;
    int i1  = i0 + NN / 2;
    int j0  = blockIdx.y * JTILE;
    int lane = tid & 31, wid = tid >> 5;

    if (tid < JT2) {
        int j = j0 + 2 * tid;
        float w0 = (lbl[j]     == 0) ? w[j]     : 0.0f;
        float w1 = (lbl[j + 1] == 0) ? w[j + 1] : 0.0f;
        ulonglong2 v;
        v.x = f2pack(-x[j], -x[j + 1]);
        v.y = f2pack(-y[j], -y[j + 1]);
        sxy[tid] = v;
        sw2[tid] = f2pack(w0, w1);
    }
    __syncthreads();

    float xi0f = x[i0], xi1f = x[i1];
    float yi0f = y[i0], yi1f = y[i1];
    u64 xi0 = f2pack(xi0f, xi0f);
    u64 xi1 = f2pack(xi1f, xi1f);
    u64 yi0 = f2pack(yi0f, yi0f);
    u64 yi1 = f2pack(yi1f, yi1f);

    u64 ra0 = 0ull, rb0 = 0ull, t0 = 0ull;
    u64 ra1 = 0ull, rb1 = 0ull, t1 = 0ull;

    #pragma unroll 4
    for (int k = 0; k < JT2; k++) {
        ulonglong2 v = sxy[k];
        u64 w2 = sw2[k];

        u64 aa0 = addx2(xi0, v.x) & ABS2;   // |x_i0 - x_j| x2
        u64 ab0 = addx2(yi0, v.y) & ABS2;
        u64 u0  = mulx2(w2, aa0);
        ra0 = addx2(ra0, u0);
        rb0 = fmax2(w2, ab0, rb0);
        t0  = fmax2(u0, ab0, t0);

        u64 aa1 = addx2(xi1, v.x) & ABS2;
        u64 ab1 = addx2(yi1, v.y) & ABS2;
        u64 u1  = mulx2(w2, aa1);
        ra1 = addx2(ra1, u1);
        rb1 = fmax2(w2, ab1, rb1);
        t1  = fmax2(u1, ab1, t1);
    }

    float lo, hi;
    f2unpack(ra0, lo, hi); float raf0 = lo + hi;
    f2unpack(rb0, lo, hi); float rbf0 = lo + hi;
    f2unpack(t0,  lo, hi); float tf0  = lo + hi;
    f2unpack(ra1, lo, hi); float raf1 = lo + hi;
    f2unpack(rb1, lo, hi); float rbf1 = lo + hi;
    f2unpack(t1,  lo, hi); float tf1  = lo + hi;

    int by = blockIdx.y;
    g_RaP[by][i0] = raf0;
    g_RbP[by][i0] = rbf0;
    g_RaP[by][i1] = raf1;
    g_RbP[by][i1] = rbf1;

    // T_ab partial, weighted by wm_i (recomputed inline), per-block slot
    float wmi0 = (lbl[i0] == 0) ? w[i0] : 0.0f;
    float wmi1 = (lbl[i1] == 0) ? w[i1] : 0.0f;
    double tp = (double)(wmi0 * tf0) + (double)(wmi1 * tf1);
    tp = warp_red_d(tp);
    if (lane == 0) sred[wid] = tp;
    __syncthreads();
    if (tid == 0) {
        double s = 0.0;
        #pragma unroll
        for (int ww = 0; ww < TPB / 32; ww++) s += sred[ww];
        g_tab_part[by * IBLK2 + blockIdx.x] = s;
    }
}

// ---------------- kernel 2: full epilogue (prep + per-i + combine) ----------------
// Quantities: 0:bce 1:nf 2:sw 3:swx 4:swx2 5:swy 6:swy2 7:va 8:vb 9:uab 10:uaa 11:ubb
__global__ void k_epi(const float* __restrict__ x, const int* __restrict__ lbl,
                      const float* __restrict__ y, const float* __restrict__ w,
                      float* __restrict__ out) {
    __shared__ double sm[TPB][NQ];     // 24KB: simultaneous tree-reduce of all 12
    __shared__ bool isLast;
    int tid = threadIdx.x;
    int i = blockIdx.x * TPB + tid;

    // sum the 64 row-sum partials for this i (coalesced, L2-resident)
    float Ra = 0.0f, Rb = 0.0f;
    #pragma unroll 8
    for (int k = 0; k < JCH; k++) {
        Ra += g_RaP[k][i];
        Rb += g_RbP[k][i];
    }

    float xi = x[i];
    float yi = y[i];
    float wi = w[i];
    int   li = lbl[i];

    float m  = (li == 0) ? 1.0f : 0.0f;
    float wm = wi * m;

    // BCE term (torch F.binary_cross_entropy with clamp at -100, weighted)
    float yf     = (float)li;
    float logp   = fmaxf(logf(xi), -100.0f);
    float log1mp = fmaxf(log1pf(-xi), -100.0f);
    float bce    = wi * (-(yf * logp + (1.0f - yf) * log1mp));

    double dwm = (double)wm, dRa = (double)Ra, dRb = (double)Rb;
    sm[tid][0]  = (double)bce;
    sm[tid][1]  = (double)m;
    sm[tid][2]  = dwm;
    sm[tid][3]  = dwm * xi;
    sm[tid][4]  = dwm * xi * xi;
    sm[tid][5]  = dwm * yi;
    sm[tid][6]  = dwm * yi * yi;
    sm[tid][7]  = dwm * dRa;
    sm[tid][8]  = dwm * dRb;
    sm[tid][9]  = dwm * dRa * dRb;
    sm[tid][10] = dwm * dRa * dRa;
    sm[tid][11] = dwm * dRb * dRb;
    __syncthreads();

    // tree-reduce all 12 quantities at once
    for (int s = TPB / 2; s > 0; s >>= 1) {
        if (tid < s) {
            #pragma unroll
            for (int k = 0; k < NQ; k++) sm[tid][k] += sm[tid + s][k];
        }
        __syncthreads();
    }
    if (tid < NQ) g_epi_part[blockIdx.x][tid] = sm[0][tid];

    if (tid == 0) {
        __threadfence();
        int c = atomicAdd(&g_count, 1);
        isLast = (c == IBLK - 1);
    }
    __syncthreads();
    if (!isLast) return;

    // ---- last block: gather all partials and combine ----
    __threadfence();

    // parallel sum of the 1024 T_ab partials (reuse sm column 0)
    double tab = 0.0;
    for (int k = tid; k < NPB; k += TPB) tab += g_tab_part[k];
    sm[tid][0] = tab;
    __syncthreads();
    for (int s = TPB / 2; s > 0; s >>= 1) {
        if (tid < s) sm[tid][0] += sm[tid + s][0];
        __syncthreads();
    }
    double TAB = sm[0][0];
    __syncthreads();

    // threads 0..11 each sum one quantity across the 32 blocks
    __shared__ double q[NQ];
    if (tid < NQ) {
        double s = 0.0;
        #pragma unroll
        for (int b = 0; b < IBLK; b++) s += g_epi_part[b][tid];
        q[tid] = s;
    }
    __syncthreads();

    if (tid == 0) {
        double bce_sum = q[0], nf = q[1], sw = q[2];
        double swx = q[3], swx2 = q[4], swy = q[5], swy2 = q[6];
        double VA = q[7], VB = q[8], UAB = q[9], UAA = q[10], UBB = q[11];

        // closed forms for sum_ij wm_i wm_j (dx)^2 and (dy)^2
        double Taa = 2.0 * (sw * swx2 - swx * swx);
        double Tbb = 2.0 * (sw * swy2 - swy * swy);

        // Full weighted double-centering expansion (sw != nf!):
        //   <A.B> = Tab - (4/nf - 2*sw/nf^2) * uab + c * va*vb
        //   c     = (4 - 4*sw/nf + (sw/nf)^2) / nf^2
        double inv_nf = 1.0 / nf;
        double r      = sw * inv_nf;
        double coef_u = (4.0 - 2.0 * r) * inv_nf;
        double c      = (4.0 - 4.0 * r + r * r) * inv_nf * inv_nf;

        double Eab = TAB - coef_u * UAB + c * VA * VB;
        double Eaa = Taa - coef_u * UAA + c * VA * VA;
        double Ebb = Tbb - coef_u * UBB + c * VB * VB;

        // the /nf^2 normalizations cancel in the ratio
        double dcorr = (Eab * Eab) / (Eaa * Ebb);   // DCORR_POWER == 2
        double bce   = bce_sum / (double)NN;
        double disco = 0.1 * dcorr;                 // DISCO_LAMBDA

        out[0] = (float)(bce + disco);
        out[1] = (float)bce;
        out[2] = (float)disco;

        g_count = 0;   // reset for next graph replay
    }
}

// ---------------- launch ----------------
extern "C" void kernel_launch(void* const* d_in, const int* in_sizes, int n_in,
                              void* d_out, int out_size) {
    const float* inferences   = (const float*)d_in[0];
    const int*   labels       = (const int*)d_in[1];
    const float* disco_target = (const float*)d_in[2];
    const float* weights      = (const float*)d_in[3];
    float* out = (float*)d_out;

    k_pairs<<<dim3(IBLK2, JCH), TPB>>>(inferences, labels, disco_target, weights);
    k_epi<<<IBLK, TPB>>>(inferences, labels, disco_target, weights, out);
}